// round 14
// baseline (speedup 1.0000x reference)
#include <cuda_runtime.h>
#include <cuda_fp16.h>
#include <cstdint>

#define BQ 8
#define LQ 4096
#define DQ 512
#define D4Q 2048
#define MQ (BQ*LQ)
#define EPSQ 1e-5f

// ======================= scratch (device globals) =======================
__device__ __align__(128) __half g_xa[(size_t)MQ*DQ];
__device__ __align__(128) __half g_c1[(size_t)MQ*DQ];
__device__ __align__(128) __half g_c2[(size_t)MQ*DQ];
__device__ __align__(128) __half g_hh[(size_t)MQ*DQ];
__device__ __align__(128) float  g_hf[(size_t)MQ*DQ];
__device__ __align__(128) __half g_t [(size_t)MQ*D4Q];
__device__ __align__(128) float  g_mlp[(size_t)MQ*DQ];
__device__ __align__(128) __half g_wc[15*DQ*DQ];          // conv W [tap][o][c]
__device__ __align__(128) __half g_w1[(size_t)D4Q*DQ];    // [o][c]
__device__ __align__(128) __half g_w2[(size_t)DQ*D4Q];    // [o][k]

// ======================= helpers =======================
__device__ __forceinline__ uint32_t smem_to_u32(const void* p) {
    uint32_t a;
    asm("{ .reg .u64 t; cvta.to.shared.u64 t, %1; cvt.u32.u64 %0, t; }" : "=r"(a) : "l"(p));
    return a;
}
#define LDSM4(r, addr) \
    asm volatile("ldmatrix.sync.aligned.m8n8.x4.shared.b16 {%0,%1,%2,%3}, [%4];" \
        : "=r"((r)[0]), "=r"((r)[1]), "=r"((r)[2]), "=r"((r)[3]) : "r"(addr))

__device__ __forceinline__ void mma_f16(float* c, const uint32_t* a, uint32_t b0, uint32_t b1) {
    asm volatile(
        "mma.sync.aligned.m16n8k16.row.col.f32.f16.f16.f32 "
        "{%0,%1,%2,%3}, {%4,%5,%6,%7}, {%8,%9}, {%0,%1,%2,%3};"
        : "+f"(c[0]), "+f"(c[1]), "+f"(c[2]), "+f"(c[3])
        : "r"(a[0]), "r"(a[1]), "r"(a[2]), "r"(a[3]), "r"(b0), "r"(b1));
}
__device__ __forceinline__ void cp16(uint32_t dst, const void* src, bool pred) {
    int sz = pred ? 16 : 0;
    asm volatile("cp.async.cg.shared.global [%0], [%1], 16, %2;"
        :: "r"(dst), "l"(src), "r"(sz));
}
#define CP_COMMIT() asm volatile("cp.async.commit_group;" ::: "memory")
#define CP_WAIT1()  asm volatile("cp.async.wait_group 1;" ::: "memory")

__device__ __forceinline__ float gelu_tanh(float v) {
    float v3 = v * v * v;
    return 0.5f * v * (1.f + tanhf(0.7978845608028654f * (v + 0.044715f * v3)));
}

// ======================= prep kernels =======================
// All three conv weight sets in ONE launch.
// W(o,c,k) -> wc[tap][o][c] for K=3 (off 0), K=5 (off 3), K=7 (off 8)
__global__ void prep_conv_all(const float* __restrict__ W3,
                              const float* __restrict__ W5,
                              const float* __restrict__ W7,
                              __half* __restrict__ o) {
    int idx = blockIdx.x * blockDim.x + threadIdx.x;
    if (idx >= DQ * DQ) return;
    const float* s3 = W3 + (size_t)idx * 3;
    const float* s5 = W5 + (size_t)idx * 5;
    const float* s7 = W7 + (size_t)idx * 7;
    #pragma unroll
    for (int k = 0; k < 3; k++)
        o[(size_t)k * DQ * DQ + idx] = __float2half_rn(s3[k]);
    #pragma unroll
    for (int k = 0; k < 5; k++)
        o[(size_t)(3 + k) * DQ * DQ + idx] = __float2half_rn(s5[k]);
    #pragma unroll
    for (int k = 0; k < 7; k++)
        o[(size_t)(8 + k) * DQ * DQ + idx] = __float2half_rn(s7[k]);
}
// tiled transpose: in[R][C] fp32 -> out[C][R] half
__global__ void transpose_f2h(const float* __restrict__ in, __half* __restrict__ out,
                              int R, int C) {
    __shared__ float tile[32][33];
    const int c0 = blockIdx.x * 32, r0 = blockIdx.y * 32;
    const int tx = threadIdx.x, ty = threadIdx.y;    // 32 x 8
    #pragma unroll
    for (int i = 0; i < 32; i += 8)
        tile[ty + i][tx] = in[(size_t)(r0 + ty + i) * C + c0 + tx];
    __syncthreads();
    #pragma unroll
    for (int i = 0; i < 32; i += 8)
        out[(size_t)(c0 + ty + i) * R + r0 + tx] = __float2half_rn(tile[tx][ty + i]);
}
// x fp32 -> fp16, 4x float4 per thread (MLP=4)
__global__ void convert_x(const float* __restrict__ x, __half* __restrict__ o) {
    size_t base = ((size_t)blockIdx.x * blockDim.x + threadIdx.x) * 16;
    float4 v[4];
    #pragma unroll
    for (int p = 0; p < 4; p++) v[p] = *(const float4*)(x + base + p * 4);
    #pragma unroll
    for (int p = 0; p < 4; p++) {
        *(__half2*)(o + base + p * 4)     = __floats2half2_rn(v[p].x, v[p].y);
        *(__half2*)(o + base + p * 4 + 2) = __floats2half2_rn(v[p].z, v[p].w);
    }
}

// ======================= warp-MMA GEMM (R11/R13 proven config) =======================
// 128x128 CTA tile, 8 warps (4m x 2n), warp tile 32x64.
// BK=64, 3-stage cp.async, issue-ahead 2, ONE barrier per chunk, 2 CTAs/SM.
// MODE 0: conv (masked A) -> fp16 out ; MODE 1: mlp1 gelu -> fp16 ; MODE 2: mlp2 -> fp32
template<int MODE, int KTAPS, int KTOT, int NOUT>
__global__ __launch_bounds__(256, 2) void gemm_mma(
    const __half* __restrict__ Ag, const int* __restrict__ chain,
    const __half* __restrict__ Bg,
    const float* __restrict__ bias,
    float* __restrict__ outf, __half* __restrict__ outh)
{
    constexpr int PADC = (KTAPS - 1) / 2;
    constexpr int NCH  = (MODE == 0) ? KTAPS * 8 : KTOT / 64;
    constexpr int LDS_ = 72;                       // 64 + 8 pad (144B row)
    constexpr uint32_t TILE  = 128 * LDS_ * 2;     // 18432 B
    constexpr uint32_t OFF_A = 0, OFF_B = TILE;
    constexpr uint32_t STAGE = 2 * TILE;           // 36864 B ; x3 = 110592

    extern __shared__ __align__(128) char dyn[];
    __shared__ int chs[144];

    const int tid  = threadIdx.x;
    const int wid  = tid >> 5;
    const int lane = tid & 31;
    const int wm   = wid & 3;
    const int wn   = wid >> 2;
    const int bz   = blockIdx.z;
    const int l0   = blockIdx.x * 128;
    const int n0   = blockIdx.y * 128;
    const size_t arow0 = (MODE == 0) ? ((size_t)bz * LQ + l0) : (size_t)l0;
    const uint32_t smu = smem_to_u32(dyn);

    if (MODE == 0) {
        for (int i = tid; i < 128 + KTAPS - 1; i += 256) {
            int j = l0 + i - PADC;
            chs[i] = (j >= 0 && j < LQ) ? chain[bz * LQ + j] : -1;
        }
        __syncthreads();
    }

    float acc[2][8][4];
    #pragma unroll
    for (int i = 0; i < 2; i++)
        #pragma unroll
        for (int j = 0; j < 8; j++)
            #pragma unroll
            for (int q = 0; q < 4; q++) acc[i][j][q] = 0.f;

    auto issue_chunk = [&](int ci) {
        const uint32_t sb = smu + (uint32_t)(ci % 3) * STAGE;
        int tap = 0, k0;
        size_t bofs = 0;
        if (MODE == 0) { tap = ci >> 3; k0 = (ci & 7) * 64; bofs = (size_t)tap * DQ * DQ; }
        else k0 = ci * 64;
        #pragma unroll
        for (int i = 0; i < 4; i++) {          // B: 128 n-rows x 64 k
            int idx = tid + i * 256;
            int n = idx >> 3, q = idx & 7;
            size_t src = bofs + (size_t)(n0 + n) * KTOT + k0 + q * 8;
            cp16(sb + OFF_B + (uint32_t)((n * LDS_ + q * 8) * 2), Bg + src, true);
        }
        #pragma unroll
        for (int i = 0; i < 4; i++) {          // A: 128 rows x 64 k
            int idx = tid + i * 256;
            int r = idx >> 3, q = idx & 7;
            bool ok = true;
            size_t row;
            if (MODE == 0) {
                ok = (chs[r + tap] == chs[r + PADC]);
                int rr = l0 + r + tap - PADC;
                rr = rr < 0 ? 0 : (rr >= LQ ? LQ - 1 : rr);
                row = (size_t)bz * LQ + rr;
            } else {
                row = arow0 + r;
            }
            cp16(sb + OFF_A + (uint32_t)((r * LDS_ + q * 8) * 2),
                 Ag + row * (size_t)KTOT + k0 + q * 8, ok);
        }
        CP_COMMIT();
    };

    const int rsel = (lane & 7) + ((lane >> 3) & 1) * 8;
    const int ksel = (lane >> 4) * 8;

    issue_chunk(0);
    if (NCH > 1) issue_chunk(1); else CP_COMMIT();

    for (int ci = 0; ci < NCH; ci++) {
        CP_WAIT1();
        __syncthreads();

        // start next loads ASAP (stage (ci+2)%3 was last read at ci-1; entry
        // barrier above guarantees all warps are past that compute)
        if (ci + 2 < NCH) issue_chunk(ci + 2);
        else CP_COMMIT();

        const uint32_t sb = smu + (uint32_t)(ci % 3) * STAGE;
        #pragma unroll
        for (int ks = 0; ks < 4; ks++) {
            const int kb = ks * 16 + ksel;
            uint32_t af[2][4];
            uint32_t bf[4][4];
            #pragma unroll
            for (int mi = 0; mi < 2; mi++) {
                uint32_t off = (uint32_t)(((wm * 32 + mi * 16 + rsel) * LDS_ + kb) * 2);
                LDSM4(af[mi], sb + OFF_A + off);
            }
            #pragma unroll
            for (int np = 0; np < 4; np++) {
                uint32_t off = (uint32_t)(((wn * 64 + np * 16 + rsel) * LDS_ + kb) * 2);
                LDSM4(bf[np], sb + OFF_B + off);
            }
            #pragma unroll
            for (int mi = 0; mi < 2; mi++)
                #pragma unroll
                for (int np = 0; np < 4; np++) {
                    mma_f16(acc[mi][np * 2],     af[mi], bf[np][0], bf[np][2]);
                    mma_f16(acc[mi][np * 2 + 1], af[mi], bf[np][1], bf[np][3]);
                }
        }
    }

    // ---- epilogue ----
    const int g = lane >> 2, t = lane & 3;
    #pragma unroll
    for (int mi = 0; mi < 2; mi++) {
        #pragma unroll
        for (int nj = 0; nj < 8; nj++) {
            const int col = n0 + wn * 64 + nj * 8 + t * 2;
            const size_t r0 = arow0 + wm * 32 + mi * 16 + g;
            const float b0v = bias[col], b1v = bias[col + 1];
            float u0 = acc[mi][nj][0] + b0v, u1 = acc[mi][nj][1] + b1v;
            float u2 = acc[mi][nj][2] + b0v, u3 = acc[mi][nj][3] + b1v;
            if (MODE == 1) {
                u0 = gelu_tanh(u0); u1 = gelu_tanh(u1);
                u2 = gelu_tanh(u2); u3 = gelu_tanh(u3);
            }
            if (MODE == 2) {
                *(float2*)(outf + r0 * (size_t)NOUT + col)       = make_float2(u0, u1);
                *(float2*)(outf + (r0 + 8) * (size_t)NOUT + col) = make_float2(u2, u3);
            } else {
                *(__half2*)(outh + r0 * (size_t)NOUT + col)       = __floats2half2_rn(u0, u1);
                *(__half2*)(outh + (r0 + 8) * (size_t)NOUT + col) = __floats2half2_rn(u2, u3);
            }
        }
    }
}

// ======================= LN kernels (warp-per-row, no smem/barrier) =======================
// LN1: v = x(fp32) + conv(fp16); out -> h fp16 + h fp32. 8 rows per 256-thr block.
__global__ __launch_bounds__(256) void ln1_kernel(
    const float* __restrict__ x, const __half* __restrict__ cv,
    const float* __restrict__ g, const float* __restrict__ beta,
    __half* __restrict__ oh, float* __restrict__ of)
{
    const int warp = threadIdx.x >> 5;
    const int lane = threadIdx.x & 31;
    const size_t row = (size_t)blockIdx.x * 8 + warp;
    const size_t rb = row * DQ;

    float v[16];
    #pragma unroll
    for (int p = 0; p < 4; p++) {
        const size_t off = rb + p * 128 + lane * 4;
        float4 a = *(const float4*)(x + off);
        __half2 c0 = *(const __half2*)(cv + off);
        __half2 c1 = *(const __half2*)(cv + off + 2);
        v[p*4+0] = a.x + __half2float(c0.x);
        v[p*4+1] = a.y + __half2float(c0.y);
        v[p*4+2] = a.z + __half2float(c1.x);
        v[p*4+3] = a.w + __half2float(c1.y);
    }
    float s = 0.f, sq = 0.f;
    #pragma unroll
    for (int i = 0; i < 16; i++) { s += v[i]; sq += v[i] * v[i]; }
    #pragma unroll
    for (int off = 16; off; off >>= 1) {
        s  += __shfl_xor_sync(0xffffffffu, s,  off);
        sq += __shfl_xor_sync(0xffffffffu, sq, off);
    }
    const float mu  = s * (1.f / DQ);
    const float var = sq * (1.f / DQ) - mu * mu;
    const float rs  = rsqrtf(var + EPSQ);

    #pragma unroll
    for (int p = 0; p < 4; p++) {
        const size_t off = rb + p * 128 + lane * 4;
        const int c = p * 128 + lane * 4;
        float4 g4 = *(const float4*)(g + c);
        float4 b4 = *(const float4*)(beta + c);
        float o0 = (v[p*4+0] - mu) * rs * g4.x + b4.x;
        float o1 = (v[p*4+1] - mu) * rs * g4.y + b4.y;
        float o2 = (v[p*4+2] - mu) * rs * g4.z + b4.z;
        float o3 = (v[p*4+3] - mu) * rs * g4.w + b4.w;
        *(__half2*)(oh + off)     = __floats2half2_rn(o0, o1);
        *(__half2*)(oh + off + 2) = __floats2half2_rn(o2, o3);
        *(float4*)(of + off) = make_float4(o0, o1, o2, o3);
    }
}

// LN2: v = h(fp32) + mlp(fp32); out fp32. 8 rows per 256-thr block.
__global__ __launch_bounds__(256) void ln2_kernel(
    const float* __restrict__ hin, const float* __restrict__ m,
    const float* __restrict__ g, const float* __restrict__ beta,
    float* __restrict__ out)
{
    const int warp = threadIdx.x >> 5;
    const int lane = threadIdx.x & 31;
    const size_t row = (size_t)blockIdx.x * 8 + warp;
    const size_t rb = row * DQ;

    float v[16];
    #pragma unroll
    for (int p = 0; p < 4; p++) {
        const size_t off = rb + p * 128 + lane * 4;
        float4 a = *(const float4*)(hin + off);
        float4 b = *(const float4*)(m + off);
        v[p*4+0] = a.x + b.x;
        v[p*4+1] = a.y + b.y;
        v[p*4+2] = a.z + b.z;
        v[p*4+3] = a.w + b.w;
    }
    float s = 0.f, sq = 0.f;
    #pragma unroll
    for (int i = 0; i < 16; i++) { s += v[i]; sq += v[i] * v[i]; }
    #pragma unroll
    for (int off = 16; off; off >>= 1) {
        s  += __shfl_xor_sync(0xffffffffu, s,  off);
        sq += __shfl_xor_sync(0xffffffffu, sq, off);
    }
    const float mu  = s * (1.f / DQ);
    const float var = sq * (1.f / DQ) - mu * mu;
    const float rs  = rsqrtf(var + EPSQ);

    #pragma unroll
    for (int p = 0; p < 4; p++) {
        const size_t off = rb + p * 128 + lane * 4;
        const int c = p * 128 + lane * 4;
        float4 g4 = *(const float4*)(g + c);
        float4 b4 = *(const float4*)(beta + c);
        float4 o4;
        o4.x = (v[p*4+0] - mu) * rs * g4.x + b4.x;
        o4.y = (v[p*4+1] - mu) * rs * g4.y + b4.y;
        o4.z = (v[p*4+2] - mu) * rs * g4.z + b4.z;
        o4.w = (v[p*4+3] - mu) * rs * g4.w + b4.w;
        *(float4*)(out + off) = o4;
    }
}

// ======================= launch =======================
extern "C" void kernel_launch(void* const* d_in, const int* in_sizes, int n_in,
                              void* d_out, int out_size) {
    const float* x    = (const float*)d_in[0];
    const int*   chain= (const int*)  d_in[1];
    const float* W3   = (const float*)d_in[2];
    const float* b3   = (const float*)d_in[3];
    const float* W5   = (const float*)d_in[4];
    const float* b5   = (const float*)d_in[5];
    const float* W7   = (const float*)d_in[6];
    const float* b7   = (const float*)d_in[7];
    const float* w1   = (const float*)d_in[8];
    const float* bm1  = (const float*)d_in[9];
    const float* w2   = (const float*)d_in[10];
    const float* bm2  = (const float*)d_in[11];
    const float* g1   = (const float*)d_in[12];
    const float* be1  = (const float*)d_in[13];
    const float* g2   = (const float*)d_in[14];
    const float* be2  = (const float*)d_in[15];
    float* out = (float*)d_out;

    __half *xa, *c1, *c2, *hh, *t, *wc, *w1p, *w2p;
    float *hf, *mlpf;
    cudaGetSymbolAddress((void**)&xa, g_xa);
    cudaGetSymbolAddress((void**)&c1, g_c1);
    cudaGetSymbolAddress((void**)&c2, g_c2);
    cudaGetSymbolAddress((void**)&hh, g_hh);
    cudaGetSymbolAddress((void**)&hf, g_hf);
    cudaGetSymbolAddress((void**)&t,  g_t);
    cudaGetSymbolAddress((void**)&mlpf, g_mlp);
    cudaGetSymbolAddress((void**)&wc,  g_wc);
    cudaGetSymbolAddress((void**)&w1p, g_w1);
    cudaGetSymbolAddress((void**)&w2p, g_w2);

    const int SMEMSZ = 3 * 2 * 128 * 72 * 2;   // 110592 B -> 2 CTAs/SM
    cudaFuncSetAttribute(gemm_mma<0,3,DQ,DQ>,  cudaFuncAttributeMaxDynamicSharedMemorySize, SMEMSZ);
    cudaFuncSetAttribute(gemm_mma<0,5,DQ,DQ>,  cudaFuncAttributeMaxDynamicSharedMemorySize, SMEMSZ);
    cudaFuncSetAttribute(gemm_mma<0,7,DQ,DQ>,  cudaFuncAttributeMaxDynamicSharedMemorySize, SMEMSZ);
    cudaFuncSetAttribute(gemm_mma<1,1,DQ,D4Q>, cudaFuncAttributeMaxDynamicSharedMemorySize, SMEMSZ);
    cudaFuncSetAttribute(gemm_mma<2,1,D4Q,DQ>, cudaFuncAttributeMaxDynamicSharedMemorySize, SMEMSZ);

    // prep
    prep_conv_all<<<(DQ*DQ + 255)/256, 256>>>(W3, W5, W7, wc);
    transpose_f2h<<<dim3(D4Q/32, DQ/32), dim3(32, 8)>>>(w1, w1p, DQ, D4Q);
    transpose_f2h<<<dim3(DQ/32, D4Q/32), dim3(32, 8)>>>(w2, w2p, D4Q, DQ);
    convert_x<<<MQ*DQ/16/256, 256>>>(x, xa);

    // conv chain
    dim3 cgrid(LQ/128, DQ/128, BQ);
    gemm_mma<0,3,DQ,DQ><<<cgrid, 256, SMEMSZ>>>(xa, chain, wc,           b3, nullptr, c1);
    gemm_mma<0,5,DQ,DQ><<<cgrid, 256, SMEMSZ>>>(c1, chain, wc + 3*DQ*DQ, b5, nullptr, c2);
    gemm_mma<0,7,DQ,DQ><<<cgrid, 256, SMEMSZ>>>(c2, chain, wc + 8*DQ*DQ, b7, nullptr, c1);

    // h = LN1(x + conv)
    ln1_kernel<<<MQ/8, 256>>>(x, c1, g1, be1, hh, hf);

    // MLP
    gemm_mma<1,1,DQ,D4Q><<<dim3(MQ/128, D4Q/128, 1), 256, SMEMSZ>>>(hh, nullptr, w1p, bm1, nullptr, t);
    gemm_mma<2,1,D4Q,DQ><<<dim3(MQ/128, DQ/128, 1),  256, SMEMSZ>>>(t,  nullptr, w2p, bm2, mlpf, nullptr);

    // out = LN2(h + mlp)
    ln2_kernel<<<MQ/8, 256>>>(hf, mlpf, g2, be2, out);
}

// round 15
// speedup vs baseline: 1.0258x; 1.0258x over previous
#include <cuda_runtime.h>
#include <cuda_fp16.h>
#include <cstdint>

#define BQ 8
#define LQ 4096
#define DQ 512
#define D4Q 2048
#define MQ (BQ*LQ)
#define EPSQ 1e-5f

// ======================= scratch (device globals) =======================
__device__ __align__(128) __half g_xa[(size_t)MQ*DQ];
__device__ __align__(128) __half g_c1[(size_t)MQ*DQ];
__device__ __align__(128) __half g_c2[(size_t)MQ*DQ];
__device__ __align__(128) __half g_hh[(size_t)MQ*DQ];
__device__ __align__(128) __half g_t [(size_t)MQ*D4Q];
__device__ __align__(128) __half g_wc[15*DQ*DQ];          // conv W [tap][o][c]
__device__ __align__(128) __half g_w1[(size_t)D4Q*DQ];    // [o][c]
__device__ __align__(128) __half g_w2[(size_t)DQ*D4Q];    // [o][k]

// ======================= helpers =======================
__device__ __forceinline__ uint32_t smem_to_u32(const void* p) {
    uint32_t a;
    asm("{ .reg .u64 t; cvta.to.shared.u64 t, %1; cvt.u32.u64 %0, t; }" : "=r"(a) : "l"(p));
    return a;
}
#define LDSM4(r, addr) \
    asm volatile("ldmatrix.sync.aligned.m8n8.x4.shared.b16 {%0,%1,%2,%3}, [%4];" \
        : "=r"((r)[0]), "=r"((r)[1]), "=r"((r)[2]), "=r"((r)[3]) : "r"(addr))

__device__ __forceinline__ void mma_f16(float* c, const uint32_t* a, uint32_t b0, uint32_t b1) {
    asm volatile(
        "mma.sync.aligned.m16n8k16.row.col.f32.f16.f16.f32 "
        "{%0,%1,%2,%3}, {%4,%5,%6,%7}, {%8,%9}, {%0,%1,%2,%3};"
        : "+f"(c[0]), "+f"(c[1]), "+f"(c[2]), "+f"(c[3])
        : "r"(a[0]), "r"(a[1]), "r"(a[2]), "r"(a[3]), "r"(b0), "r"(b1));
}
__device__ __forceinline__ void cp16(uint32_t dst, const void* src, bool pred) {
    int sz = pred ? 16 : 0;
    asm volatile("cp.async.cg.shared.global [%0], [%1], 16, %2;"
        :: "r"(dst), "l"(src), "r"(sz));
}
#define CP_COMMIT() asm volatile("cp.async.commit_group;" ::: "memory")
#define CP_WAIT1()  asm volatile("cp.async.wait_group 1;" ::: "memory")

__device__ __forceinline__ float gelu_tanh(float v) {
    float v3 = v * v * v;
    return 0.5f * v * (1.f + tanhf(0.7978845608028654f * (v + 0.044715f * v3)));
}

// ======================= prep kernels =======================
// All three conv weight sets in ONE launch: W(o,c,k) -> wc[tap][o][c]
__global__ void prep_conv_all(const float* __restrict__ W3,
                              const float* __restrict__ W5,
                              const float* __restrict__ W7,
                              __half* __restrict__ o) {
    int idx = blockIdx.x * blockDim.x + threadIdx.x;
    if (idx >= DQ * DQ) return;
    const float* s3 = W3 + (size_t)idx * 3;
    const float* s5 = W5 + (size_t)idx * 5;
    const float* s7 = W7 + (size_t)idx * 7;
    #pragma unroll
    for (int k = 0; k < 3; k++)
        o[(size_t)k * DQ * DQ + idx] = __float2half_rn(s3[k]);
    #pragma unroll
    for (int k = 0; k < 5; k++)
        o[(size_t)(3 + k) * DQ * DQ + idx] = __float2half_rn(s5[k]);
    #pragma unroll
    for (int k = 0; k < 7; k++)
        o[(size_t)(8 + k) * DQ * DQ + idx] = __float2half_rn(s7[k]);
}
// tiled transpose: in[R][C] fp32 -> out[C][R] half
__global__ void transpose_f2h(const float* __restrict__ in, __half* __restrict__ out,
                              int R, int C) {
    __shared__ float tile[32][33];
    const int c0 = blockIdx.x * 32, r0 = blockIdx.y * 32;
    const int tx = threadIdx.x, ty = threadIdx.y;    // 32 x 8
    #pragma unroll
    for (int i = 0; i < 32; i += 8)
        tile[ty + i][tx] = in[(size_t)(r0 + ty + i) * C + c0 + tx];
    __syncthreads();
    #pragma unroll
    for (int i = 0; i < 32; i += 8)
        out[(size_t)(c0 + ty + i) * R + r0 + tx] = __float2half_rn(tile[tx][ty + i]);
}
// x fp32 -> fp16 (R13-proven 1x float4/thread)
__global__ void convert_x(const float* __restrict__ x, __half* __restrict__ o) {
    size_t idx = (size_t)blockIdx.x * blockDim.x + threadIdx.x;
    float4 v = *(const float4*)(x + idx * 4);
    *(__half2*)(o + idx * 4)     = __floats2half2_rn(v.x, v.y);
    *(__half2*)(o + idx * 4 + 2) = __floats2half2_rn(v.z, v.w);
}

// ======================= warp-MMA GEMM (R11/R13 proven config) =======================
// 128x128 CTA tile, 8 warps (4m x 2n), warp tile 32x64.
// BK=64, 3-stage cp.async, issue-ahead 2, ONE barrier per chunk, 2 CTAs/SM.
// MODE 0: conv (masked A) -> fp16 out ; MODE 1: mlp1 gelu -> fp16 ; MODE 2: mlp2 -> fp16
template<int MODE, int KTAPS, int KTOT, int NOUT>
__global__ __launch_bounds__(256, 2) void gemm_mma(
    const __half* __restrict__ Ag, const int* __restrict__ chain,
    const __half* __restrict__ Bg,
    const float* __restrict__ bias,
    __half* __restrict__ outh)
{
    constexpr int PADC = (KTAPS - 1) / 2;
    constexpr int NCH  = (MODE == 0) ? KTAPS * 8 : KTOT / 64;
    constexpr int LDS_ = 72;                       // 64 + 8 pad (144B row)
    constexpr uint32_t TILE  = 128 * LDS_ * 2;     // 18432 B
    constexpr uint32_t OFF_A = 0, OFF_B = TILE;
    constexpr uint32_t STAGE = 2 * TILE;           // 36864 B ; x3 = 110592

    extern __shared__ __align__(128) char dyn[];
    __shared__ int chs[144];

    const int tid  = threadIdx.x;
    const int wid  = tid >> 5;
    const int lane = tid & 31;
    const int wm   = wid & 3;
    const int wn   = wid >> 2;
    const int bz   = blockIdx.z;
    const int l0   = blockIdx.x * 128;
    const int n0   = blockIdx.y * 128;
    const size_t arow0 = (MODE == 0) ? ((size_t)bz * LQ + l0) : (size_t)l0;
    const uint32_t smu = smem_to_u32(dyn);

    if (MODE == 0) {
        for (int i = tid; i < 128 + KTAPS - 1; i += 256) {
            int j = l0 + i - PADC;
            chs[i] = (j >= 0 && j < LQ) ? chain[bz * LQ + j] : -1;
        }
        __syncthreads();
    }

    float acc[2][8][4];
    #pragma unroll
    for (int i = 0; i < 2; i++)
        #pragma unroll
        for (int j = 0; j < 8; j++)
            #pragma unroll
            for (int q = 0; q < 4; q++) acc[i][j][q] = 0.f;

    auto issue_chunk = [&](int ci) {
        const uint32_t sb = smu + (uint32_t)(ci % 3) * STAGE;
        int tap = 0, k0;
        size_t bofs = 0;
        if (MODE == 0) { tap = ci >> 3; k0 = (ci & 7) * 64; bofs = (size_t)tap * DQ * DQ; }
        else k0 = ci * 64;
        #pragma unroll
        for (int i = 0; i < 4; i++) {          // B: 128 n-rows x 64 k
            int idx = tid + i * 256;
            int n = idx >> 3, q = idx & 7;
            size_t src = bofs + (size_t)(n0 + n) * KTOT + k0 + q * 8;
            cp16(sb + OFF_B + (uint32_t)((n * LDS_ + q * 8) * 2), Bg + src, true);
        }
        #pragma unroll
        for (int i = 0; i < 4; i++) {          // A: 128 rows x 64 k
            int idx = tid + i * 256;
            int r = idx >> 3, q = idx & 7;
            bool ok = true;
            size_t row;
            if (MODE == 0) {
                ok = (chs[r + tap] == chs[r + PADC]);
                int rr = l0 + r + tap - PADC;
                rr = rr < 0 ? 0 : (rr >= LQ ? LQ - 1 : rr);
                row = (size_t)bz * LQ + rr;
            } else {
                row = arow0 + r;
            }
            cp16(sb + OFF_A + (uint32_t)((r * LDS_ + q * 8) * 2),
                 Ag + row * (size_t)KTOT + k0 + q * 8, ok);
        }
        CP_COMMIT();
    };

    const int rsel = (lane & 7) + ((lane >> 3) & 1) * 8;
    const int ksel = (lane >> 4) * 8;

    issue_chunk(0);
    if (NCH > 1) issue_chunk(1); else CP_COMMIT();

    for (int ci = 0; ci < NCH; ci++) {
        CP_WAIT1();
        __syncthreads();

        // start next loads ASAP (stage (ci+2)%3 was last read at ci-1; entry
        // barrier above guarantees all warps are past that compute)
        if (ci + 2 < NCH) issue_chunk(ci + 2);
        else CP_COMMIT();

        const uint32_t sb = smu + (uint32_t)(ci % 3) * STAGE;
        #pragma unroll
        for (int ks = 0; ks < 4; ks++) {
            const int kb = ks * 16 + ksel;
            uint32_t af[2][4];
            uint32_t bf[4][4];
            #pragma unroll
            for (int mi = 0; mi < 2; mi++) {
                uint32_t off = (uint32_t)(((wm * 32 + mi * 16 + rsel) * LDS_ + kb) * 2);
                LDSM4(af[mi], sb + OFF_A + off);
            }
            #pragma unroll
            for (int np = 0; np < 4; np++) {
                uint32_t off = (uint32_t)(((wn * 64 + np * 16 + rsel) * LDS_ + kb) * 2);
                LDSM4(bf[np], sb + OFF_B + off);
            }
            #pragma unroll
            for (int mi = 0; mi < 2; mi++)
                #pragma unroll
                for (int np = 0; np < 4; np++) {
                    mma_f16(acc[mi][np * 2],     af[mi], bf[np][0], bf[np][2]);
                    mma_f16(acc[mi][np * 2 + 1], af[mi], bf[np][1], bf[np][3]);
                }
        }
    }

    // ---- epilogue (fp16 everywhere now) ----
    const int g = lane >> 2, t = lane & 3;
    #pragma unroll
    for (int mi = 0; mi < 2; mi++) {
        #pragma unroll
        for (int nj = 0; nj < 8; nj++) {
            const int col = n0 + wn * 64 + nj * 8 + t * 2;
            const size_t r0 = arow0 + wm * 32 + mi * 16 + g;
            const float b0v = bias[col], b1v = bias[col + 1];
            float u0 = acc[mi][nj][0] + b0v, u1 = acc[mi][nj][1] + b1v;
            float u2 = acc[mi][nj][2] + b0v, u3 = acc[mi][nj][3] + b1v;
            if (MODE == 1) {
                u0 = gelu_tanh(u0); u1 = gelu_tanh(u1);
                u2 = gelu_tanh(u2); u3 = gelu_tanh(u3);
            }
            *(__half2*)(outh + r0 * (size_t)NOUT + col)       = __floats2half2_rn(u0, u1);
            *(__half2*)(outh + (r0 + 8) * (size_t)NOUT + col) = __floats2half2_rn(u2, u3);
        }
    }
}

// ======================= LN kernels (R13 block-per-row form) =======================
// LN1: v = x(fp32) + conv(fp16); out -> h fp16 only
__global__ __launch_bounds__(128) void ln1_kernel(
    const float* __restrict__ x, const __half* __restrict__ cv,
    const float* __restrict__ g, const float* __restrict__ beta,
    __half* __restrict__ oh)
{
    const int row = blockIdx.x;
    const int tid = threadIdx.x;
    const size_t base = (size_t)row * DQ + tid * 4;

    const float4 va = *(const float4*)(x + base);
    __half2 c0 = *(const __half2*)(cv + base);
    __half2 c1 = *(const __half2*)(cv + base + 2);
    float v0 = va.x + __half2float(c0.x);
    float v1 = va.y + __half2float(c0.y);
    float v2 = va.z + __half2float(c1.x);
    float v3 = va.w + __half2float(c1.y);

    float s  = v0 + v1 + v2 + v3;
    float sq = v0*v0 + v1*v1 + v2*v2 + v3*v3;
    #pragma unroll
    for (int off = 16; off; off >>= 1) {
        s  += __shfl_xor_sync(0xffffffffu, s,  off);
        sq += __shfl_xor_sync(0xffffffffu, sq, off);
    }
    __shared__ float ws[4], wq[4];
    if ((tid & 31) == 0) { ws[tid >> 5] = s; wq[tid >> 5] = sq; }
    __syncthreads();
    s  = ws[0] + ws[1] + ws[2] + ws[3];
    sq = wq[0] + wq[1] + wq[2] + wq[3];

    const float mu  = s * (1.f / DQ);
    const float var = sq * (1.f / DQ) - mu * mu;
    const float rs  = rsqrtf(var + EPSQ);

    const float4 g4 = ((const float4*)g)[tid];
    const float4 b4 = ((const float4*)beta)[tid];
    float o0 = (v0 - mu) * rs * g4.x + b4.x;
    float o1 = (v1 - mu) * rs * g4.y + b4.y;
    float o2 = (v2 - mu) * rs * g4.z + b4.z;
    float o3 = (v3 - mu) * rs * g4.w + b4.w;

    *(__half2*)(oh + base)     = __floats2half2_rn(o0, o1);
    *(__half2*)(oh + base + 2) = __floats2half2_rn(o2, o3);
}

// LN2: v = h(fp16) + mlp(fp16); out fp32
__global__ __launch_bounds__(128) void ln2_kernel(
    const __half* __restrict__ hin, const __half* __restrict__ m,
    const float* __restrict__ g, const float* __restrict__ beta,
    float* __restrict__ out)
{
    const int row = blockIdx.x;
    const int tid = threadIdx.x;
    const size_t base = (size_t)row * DQ + tid * 4;

    __half2 a0 = *(const __half2*)(hin + base);
    __half2 a1 = *(const __half2*)(hin + base + 2);
    __half2 b0 = *(const __half2*)(m + base);
    __half2 b1 = *(const __half2*)(m + base + 2);
    float v0 = __half2float(a0.x) + __half2float(b0.x);
    float v1 = __half2float(a0.y) + __half2float(b0.y);
    float v2 = __half2float(a1.x) + __half2float(b1.x);
    float v3 = __half2float(a1.y) + __half2float(b1.y);

    float s  = v0 + v1 + v2 + v3;
    float sq = v0*v0 + v1*v1 + v2*v2 + v3*v3;
    #pragma unroll
    for (int off = 16; off; off >>= 1) {
        s  += __shfl_xor_sync(0xffffffffu, s,  off);
        sq += __shfl_xor_sync(0xffffffffu, sq, off);
    }
    __shared__ float ws[4], wq[4];
    if ((tid & 31) == 0) { ws[tid >> 5] = s; wq[tid >> 5] = sq; }
    __syncthreads();
    s  = ws[0] + ws[1] + ws[2] + ws[3];
    sq = wq[0] + wq[1] + wq[2] + wq[3];

    const float mu  = s * (1.f / DQ);
    const float var = sq * (1.f / DQ) - mu * mu;
    const float rs  = rsqrtf(var + EPSQ);

    const float4 g4 = ((const float4*)g)[tid];
    const float4 b4 = ((const float4*)beta)[tid];
    float4 o4;
    o4.x = (v0 - mu) * rs * g4.x + b4.x;
    o4.y = (v1 - mu) * rs * g4.y + b4.y;
    o4.z = (v2 - mu) * rs * g4.z + b4.z;
    o4.w = (v3 - mu) * rs * g4.w + b4.w;
    *(float4*)(out + base) = o4;
}

// ======================= launch =======================
extern "C" void kernel_launch(void* const* d_in, const int* in_sizes, int n_in,
                              void* d_out, int out_size) {
    const float* x    = (const float*)d_in[0];
    const int*   chain= (const int*)  d_in[1];
    const float* W3   = (const float*)d_in[2];
    const float* b3   = (const float*)d_in[3];
    const float* W5   = (const float*)d_in[4];
    const float* b5   = (const float*)d_in[5];
    const float* W7   = (const float*)d_in[6];
    const float* b7   = (const float*)d_in[7];
    const float* w1   = (const float*)d_in[8];
    const float* bm1  = (const float*)d_in[9];
    const float* w2   = (const float*)d_in[10];
    const float* bm2  = (const float*)d_in[11];
    const float* g1   = (const float*)d_in[12];
    const float* be1  = (const float*)d_in[13];
    const float* g2   = (const float*)d_in[14];
    const float* be2  = (const float*)d_in[15];
    float* out = (float*)d_out;

    __half *xa, *c1, *c2, *hh, *t, *wc, *w1p, *w2p;
    cudaGetSymbolAddress((void**)&xa, g_xa);
    cudaGetSymbolAddress((void**)&c1, g_c1);
    cudaGetSymbolAddress((void**)&c2, g_c2);
    cudaGetSymbolAddress((void**)&hh, g_hh);
    cudaGetSymbolAddress((void**)&t,  g_t);
    cudaGetSymbolAddress((void**)&wc,  g_wc);
    cudaGetSymbolAddress((void**)&w1p, g_w1);
    cudaGetSymbolAddress((void**)&w2p, g_w2);

    const int SMEMSZ = 3 * 2 * 128 * 72 * 2;   // 110592 B -> 2 CTAs/SM
    cudaFuncSetAttribute(gemm_mma<0,3,DQ,DQ>,  cudaFuncAttributeMaxDynamicSharedMemorySize, SMEMSZ);
    cudaFuncSetAttribute(gemm_mma<0,5,DQ,DQ>,  cudaFuncAttributeMaxDynamicSharedMemorySize, SMEMSZ);
    cudaFuncSetAttribute(gemm_mma<0,7,DQ,DQ>,  cudaFuncAttributeMaxDynamicSharedMemorySize, SMEMSZ);
    cudaFuncSetAttribute(gemm_mma<1,1,DQ,D4Q>, cudaFuncAttributeMaxDynamicSharedMemorySize, SMEMSZ);
    cudaFuncSetAttribute(gemm_mma<2,1,D4Q,DQ>, cudaFuncAttributeMaxDynamicSharedMemorySize, SMEMSZ);

    // prep
    prep_conv_all<<<(DQ*DQ + 255)/256, 256>>>(W3, W5, W7, wc);
    transpose_f2h<<<dim3(D4Q/32, DQ/32), dim3(32, 8)>>>(w1, w1p, DQ, D4Q);
    transpose_f2h<<<dim3(DQ/32, D4Q/32), dim3(32, 8)>>>(w2, w2p, D4Q, DQ);
    convert_x<<<(MQ*DQ/4 + 255)/256, 256>>>(x, xa);

    // conv chain
    dim3 cgrid(LQ/128, DQ/128, BQ);
    gemm_mma<0,3,DQ,DQ><<<cgrid, 256, SMEMSZ>>>(xa, chain, wc,           b3, c1);
    gemm_mma<0,5,DQ,DQ><<<cgrid, 256, SMEMSZ>>>(c1, chain, wc + 3*DQ*DQ, b5, c2);
    gemm_mma<0,7,DQ,DQ><<<cgrid, 256, SMEMSZ>>>(c2, chain, wc + 8*DQ*DQ, b7, c1);

    // h = LN1(x + conv) -> fp16
    ln1_kernel<<<MQ, 128>>>(x, c1, g1, be1, hh);

    // MLP (mlp2 output fp16 into c2)
    gemm_mma<1,1,DQ,D4Q><<<dim3(MQ/128, D4Q/128, 1), 256, SMEMSZ>>>(hh, nullptr, w1p, bm1, t);
    gemm_mma<2,1,D4Q,DQ><<<dim3(MQ/128, DQ/128, 1),  256, SMEMSZ>>>(t,  nullptr, w2p, bm2, c2);

    // out = LN2(h + mlp)
    ln2_kernel<<<MQ, 128>>>(hh, c2, g2, be2, out);
}

// round 17
// speedup vs baseline: 1.0342x; 1.0082x over previous
#include <cuda_runtime.h>
#include <cuda_fp16.h>
#include <cstdint>

#define BQ 8
#define LQ 4096
#define DQ 512
#define D4Q 2048
#define MQ (BQ*LQ)
#define EPSQ 1e-5f

// ======================= scratch (device globals) =======================
__device__ __align__(128) __half g_xa[(size_t)MQ*DQ];
__device__ __align__(128) __half g_c1[(size_t)MQ*DQ];
__device__ __align__(128) __half g_c2[(size_t)MQ*DQ];
__device__ __align__(128) __half g_hh[(size_t)MQ*DQ];
__device__ __align__(128) __half g_t [(size_t)MQ*D4Q];
__device__ __align__(128) __half g_wc[15*DQ*DQ];          // conv W [tap][o][c]
__device__ __align__(128) __half g_w1[(size_t)D4Q*DQ];    // [o][c]
__device__ __align__(128) __half g_w2[(size_t)DQ*D4Q];    // [o][k]

// ======================= helpers =======================
__device__ __forceinline__ uint32_t smem_to_u32(const void* p) {
    uint32_t a;
    asm("{ .reg .u64 t; cvta.to.shared.u64 t, %1; cvt.u32.u64 %0, t; }" : "=r"(a) : "l"(p));
    return a;
}
#define LDSM4(r, addr) \
    asm volatile("ldmatrix.sync.aligned.m8n8.x4.shared.b16 {%0,%1,%2,%3}, [%4];" \
        : "=r"((r)[0]), "=r"((r)[1]), "=r"((r)[2]), "=r"((r)[3]) : "r"(addr))

__device__ __forceinline__ void mma_f16(float* c, const uint32_t* a, uint32_t b0, uint32_t b1) {
    asm volatile(
        "mma.sync.aligned.m16n8k16.row.col.f32.f16.f16.f32 "
        "{%0,%1,%2,%3}, {%4,%5,%6,%7}, {%8,%9}, {%0,%1,%2,%3};"
        : "+f"(c[0]), "+f"(c[1]), "+f"(c[2]), "+f"(c[3])
        : "r"(a[0]), "r"(a[1]), "r"(a[2]), "r"(a[3]), "r"(b0), "r"(b1));
}
__device__ __forceinline__ void cp16(uint32_t dst, const void* src, bool pred) {
    int sz = pred ? 16 : 0;
    asm volatile("cp.async.cg.shared.global [%0], [%1], 16, %2;"
        :: "r"(dst), "l"(src), "r"(sz));
}
#define CP_COMMIT() asm volatile("cp.async.commit_group;" ::: "memory")
#define CP_WAIT1()  asm volatile("cp.async.wait_group 1;" ::: "memory")

__device__ __forceinline__ float gelu_tanh(float v) {
    float v3 = v * v * v;
    return 0.5f * v * (1.f + tanhf(0.7978845608028654f * (v + 0.044715f * v3)));
}

// ======================= prep kernels =======================
// All three conv weight sets in ONE launch: W(o,c,k) -> wc[tap][o][c]
__global__ void prep_conv_all(const float* __restrict__ W3,
                              const float* __restrict__ W5,
                              const float* __restrict__ W7,
                              __half* __restrict__ o) {
    int idx = blockIdx.x * blockDim.x + threadIdx.x;
    if (idx >= DQ * DQ) return;
    const float* s3 = W3 + (size_t)idx * 3;
    const float* s5 = W5 + (size_t)idx * 5;
    const float* s7 = W7 + (size_t)idx * 7;
    #pragma unroll
    for (int k = 0; k < 3; k++)
        o[(size_t)k * DQ * DQ + idx] = __float2half_rn(s3[k]);
    #pragma unroll
    for (int k = 0; k < 5; k++)
        o[(size_t)(3 + k) * DQ * DQ + idx] = __float2half_rn(s5[k]);
    #pragma unroll
    for (int k = 0; k < 7; k++)
        o[(size_t)(8 + k) * DQ * DQ + idx] = __float2half_rn(s7[k]);
}
// tiled transpose: in[R][C] fp32 -> out[C][R] half
__global__ void transpose_f2h(const float* __restrict__ in, __half* __restrict__ out,
                              int R, int C) {
    __shared__ float tile[32][33];
    const int c0 = blockIdx.x * 32, r0 = blockIdx.y * 32;
    const int tx = threadIdx.x, ty = threadIdx.y;    // 32 x 8
    #pragma unroll
    for (int i = 0; i < 32; i += 8)
        tile[ty + i][tx] = in[(size_t)(r0 + ty + i) * C + c0 + tx];
    __syncthreads();
    #pragma unroll
    for (int i = 0; i < 32; i += 8)
        out[(size_t)(c0 + ty + i) * R + r0 + tx] = __float2half_rn(tile[tx][ty + i]);
}
// x fp32 -> fp16 ; 2 coalesced float4 per thread (p-stride 1024 elems)
__global__ __launch_bounds__(256) void convert_x(const float* __restrict__ x,
                                                 __half* __restrict__ o) {
    size_t base = (size_t)blockIdx.x * 2048 + threadIdx.x * 4;
    #pragma unroll
    for (int p = 0; p < 2; p++) {
        size_t off = base + p * 1024;
        float4 v = *(const float4*)(x + off);
        *(__half2*)(o + off)     = __floats2half2_rn(v.x, v.y);
        *(__half2*)(o + off + 2) = __floats2half2_rn(v.z, v.w);
    }
}

// ======================= warp-MMA GEMM (R11/R13 proven config) =======================
// 128x128 CTA tile, 8 warps (4m x 2n), warp tile 32x64.
// BK=64, 3-stage cp.async, issue-ahead 2, ONE barrier per chunk, 2 CTAs/SM.
// MODE 0: conv (masked A) -> fp16 out ; MODE 1: mlp1 gelu -> fp16 ; MODE 2: mlp2 -> fp16
template<int MODE, int KTAPS, int KTOT, int NOUT>
__global__ __launch_bounds__(256, 2) void gemm_mma(
    const __half* __restrict__ Ag, const int* __restrict__ chain,
    const __half* __restrict__ Bg,
    const float* __restrict__ bias,
    __half* __restrict__ outh)
{
    constexpr int PADC = (KTAPS - 1) / 2;
    constexpr int NCH  = (MODE == 0) ? KTAPS * 8 : KTOT / 64;
    constexpr int LDS_ = 72;                       // 64 + 8 pad (144B row)
    constexpr uint32_t TILE  = 128 * LDS_ * 2;     // 18432 B
    constexpr uint32_t OFF_A = 0, OFF_B = TILE;
    constexpr uint32_t STAGE = 2 * TILE;           // 36864 B ; x3 = 110592

    extern __shared__ __align__(128) char dyn[];
    __shared__ int chs[144];

    const int tid  = threadIdx.x;
    const int wid  = tid >> 5;
    const int lane = tid & 31;
    const int wm   = wid & 3;
    const int wn   = wid >> 2;
    const int bz   = blockIdx.z;
    const int l0   = blockIdx.x * 128;
    const int n0   = blockIdx.y * 128;
    const size_t arow0 = (MODE == 0) ? ((size_t)bz * LQ + l0) : (size_t)l0;
    const uint32_t smu = smem_to_u32(dyn);

    if (MODE == 0) {
        for (int i = tid; i < 128 + KTAPS - 1; i += 256) {
            int j = l0 + i - PADC;
            chs[i] = (j >= 0 && j < LQ) ? chain[bz * LQ + j] : -1;
        }
        __syncthreads();
    }

    float acc[2][8][4];
    #pragma unroll
    for (int i = 0; i < 2; i++)
        #pragma unroll
        for (int j = 0; j < 8; j++)
            #pragma unroll
            for (int q = 0; q < 4; q++) acc[i][j][q] = 0.f;

    auto issue_chunk = [&](int ci) {
        const uint32_t sb = smu + (uint32_t)(ci % 3) * STAGE;
        int tap = 0, k0;
        size_t bofs = 0;
        if (MODE == 0) { tap = ci >> 3; k0 = (ci & 7) * 64; bofs = (size_t)tap * DQ * DQ; }
        else k0 = ci * 64;
        #pragma unroll
        for (int i = 0; i < 4; i++) {          // B: 128 n-rows x 64 k
            int idx = tid + i * 256;
            int n = idx >> 3, q = idx & 7;
            size_t src = bofs + (size_t)(n0 + n) * KTOT + k0 + q * 8;
            cp16(sb + OFF_B + (uint32_t)((n * LDS_ + q * 8) * 2), Bg + src, true);
        }
        #pragma unroll
        for (int i = 0; i < 4; i++) {          // A: 128 rows x 64 k
            int idx = tid + i * 256;
            int r = idx >> 3, q = idx & 7;
            bool ok = true;
            size_t row;
            if (MODE == 0) {
                ok = (chs[r + tap] == chs[r + PADC]);
                int rr = l0 + r + tap - PADC;
                rr = rr < 0 ? 0 : (rr >= LQ ? LQ - 1 : rr);
                row = (size_t)bz * LQ + rr;
            } else {
                row = arow0 + r;
            }
            cp16(sb + OFF_A + (uint32_t)((r * LDS_ + q * 8) * 2),
                 Ag + row * (size_t)KTOT + k0 + q * 8, ok);
        }
        CP_COMMIT();
    };

    const int rsel = (lane & 7) + ((lane >> 3) & 1) * 8;
    const int ksel = (lane >> 4) * 8;

    issue_chunk(0);
    if (NCH > 1) issue_chunk(1); else CP_COMMIT();

    for (int ci = 0; ci < NCH; ci++) {
        CP_WAIT1();
        __syncthreads();

        // start next loads ASAP (stage (ci+2)%3 was last read at ci-1; entry
        // barrier above guarantees all warps are past that compute)
        if (ci + 2 < NCH) issue_chunk(ci + 2);
        else CP_COMMIT();

        const uint32_t sb = smu + (uint32_t)(ci % 3) * STAGE;
        #pragma unroll
        for (int ks = 0; ks < 4; ks++) {
            const int kb = ks * 16 + ksel;
            uint32_t af[2][4];
            uint32_t bf[4][4];
            #pragma unroll
            for (int mi = 0; mi < 2; mi++) {
                uint32_t off = (uint32_t)(((wm * 32 + mi * 16 + rsel) * LDS_ + kb) * 2);
                LDSM4(af[mi], sb + OFF_A + off);
            }
            #pragma unroll
            for (int np = 0; np < 4; np++) {
                uint32_t off = (uint32_t)(((wn * 64 + np * 16 + rsel) * LDS_ + kb) * 2);
                LDSM4(bf[np], sb + OFF_B + off);
            }
            #pragma unroll
            for (int mi = 0; mi < 2; mi++)
                #pragma unroll
                for (int np = 0; np < 4; np++) {
                    mma_f16(acc[mi][np * 2],     af[mi], bf[np][0], bf[np][2]);
                    mma_f16(acc[mi][np * 2 + 1], af[mi], bf[np][1], bf[np][3]);
                }
        }
    }

    // ---- epilogue (fp16 out) ----
    const int g = lane >> 2, t = lane & 3;
    #pragma unroll
    for (int mi = 0; mi < 2; mi++) {
        #pragma unroll
        for (int nj = 0; nj < 8; nj++) {
            const int col = n0 + wn * 64 + nj * 8 + t * 2;
            const size_t r0 = arow0 + wm * 32 + mi * 16 + g;
            const float b0v = bias[col], b1v = bias[col + 1];
            float u0 = acc[mi][nj][0] + b0v, u1 = acc[mi][nj][1] + b1v;
            float u2 = acc[mi][nj][2] + b0v, u3 = acc[mi][nj][3] + b1v;
            if (MODE == 1) {
                u0 = gelu_tanh(u0); u1 = gelu_tanh(u1);
                u2 = gelu_tanh(u2); u3 = gelu_tanh(u3);
            }
            *(__half2*)(outh + r0 * (size_t)NOUT + col)       = __floats2half2_rn(u0, u1);
            *(__half2*)(outh + (r0 + 8) * (size_t)NOUT + col) = __floats2half2_rn(u2, u3);
        }
    }
}

// ======================= LN kernels (warp-per-row, no smem/barrier) =======================
// LN1: v = x(fp32) + conv(fp16); out -> h fp16. 8 rows per 256-thr block.
__global__ __launch_bounds__(256) void ln1_kernel(
    const float* __restrict__ x, const __half* __restrict__ cv,
    const float* __restrict__ g, const float* __restrict__ beta,
    __half* __restrict__ oh)
{
    const int warp = threadIdx.x >> 5;
    const int lane = threadIdx.x & 31;
    const size_t rb = ((size_t)blockIdx.x * 8 + warp) * DQ;

    float v[16];
    #pragma unroll
    for (int p = 0; p < 4; p++) {
        const size_t off = rb + p * 128 + lane * 4;
        float4 a = *(const float4*)(x + off);
        __half2 c0 = *(const __half2*)(cv + off);
        __half2 c1 = *(const __half2*)(cv + off + 2);
        v[p*4+0] = a.x + __half2float(c0.x);
        v[p*4+1] = a.y + __half2float(c0.y);
        v[p*4+2] = a.z + __half2float(c1.x);
        v[p*4+3] = a.w + __half2float(c1.y);
    }
    float s = 0.f, sq = 0.f;
    #pragma unroll
    for (int i = 0; i < 16; i++) { s += v[i]; sq += v[i] * v[i]; }
    #pragma unroll
    for (int off = 16; off; off >>= 1) {
        s  += __shfl_xor_sync(0xffffffffu, s,  off);
        sq += __shfl_xor_sync(0xffffffffu, sq, off);
    }
    const float mu  = s * (1.f / DQ);
    const float var = sq * (1.f / DQ) - mu * mu;
    const float rs  = rsqrtf(var + EPSQ);

    #pragma unroll
    for (int p = 0; p < 4; p++) {
        const size_t off = rb + p * 128 + lane * 4;
        const int c = p * 128 + lane * 4;
        float4 g4 = *(const float4*)(g + c);
        float4 b4 = *(const float4*)(beta + c);
        float o0 = (v[p*4+0] - mu) * rs * g4.x + b4.x;
        float o1 = (v[p*4+1] - mu) * rs * g4.y + b4.y;
        float o2 = (v[p*4+2] - mu) * rs * g4.z + b4.z;
        float o3 = (v[p*4+3] - mu) * rs * g4.w + b4.w;
        *(__half2*)(oh + off)     = __floats2half2_rn(o0, o1);
        *(__half2*)(oh + off + 2) = __floats2half2_rn(o2, o3);
    }
}

// LN2: v = h(fp16) + mlp(fp16); out fp32. 8 rows per 256-thr block.
__global__ __launch_bounds__(256) void ln2_kernel(
    const __half* __restrict__ hin, const __half* __restrict__ m,
    const float* __restrict__ g, const float* __restrict__ beta,
    float* __restrict__ out)
{
    const int warp = threadIdx.x >> 5;
    const int lane = threadIdx.x & 31;
    const size_t rb = ((size_t)blockIdx.x * 8 + warp) * DQ;

    float v[16];
    #pragma unroll
    for (int p = 0; p < 4; p++) {
        const size_t off = rb + p * 128 + lane * 4;
        __half2 a0 = *(const __half2*)(hin + off);
        __half2 a1 = *(const __half2*)(hin + off + 2);
        __half2 b0 = *(const __half2*)(m + off);
        __half2 b1 = *(const __half2*)(m + off + 2);
        v[p*4+0] = __half2float(a0.x) + __half2float(b0.x);
        v[p*4+1] = __half2float(a0.y) + __half2float(b0.y);
        v[p*4+2] = __half2float(a1.x) + __half2float(b1.x);
        v[p*4+3] = __half2float(a1.y) + __half2float(b1.y);
    }
    float s = 0.f, sq = 0.f;
    #pragma unroll
    for (int i = 0; i < 16; i++) { s += v[i]; sq += v[i] * v[i]; }
    #pragma unroll
    for (int off = 16; off; off >>= 1) {
        s  += __shfl_xor_sync(0xffffffffu, s,  off);
        sq += __shfl_xor_sync(0xffffffffu, sq, off);
    }
    const float mu  = s * (1.f / DQ);
    const float var = sq * (1.f / DQ) - mu * mu;
    const float rs  = rsqrtf(var + EPSQ);

    #pragma unroll
    for (int p = 0; p < 4; p++) {
        const size_t off = rb + p * 128 + lane * 4;
        const int c = p * 128 + lane * 4;
        float4 g4 = *(const float4*)(g + c);
        float4 b4 = *(const float4*)(beta + c);
        float4 o4;
        o4.x = (v[p*4+0] - mu) * rs * g4.x + b4.x;
        o4.y = (v[p*4+1] - mu) * rs * g4.y + b4.y;
        o4.z = (v[p*4+2] - mu) * rs * g4.z + b4.z;
        o4.w = (v[p*4+3] - mu) * rs * g4.w + b4.w;
        *(float4*)(out + off) = o4;
    }
}

// ======================= launch =======================
extern "C" void kernel_launch(void* const* d_in, const int* in_sizes, int n_in,
                              void* d_out, int out_size) {
    const float* x    = (const float*)d_in[0];
    const int*   chain= (const int*)  d_in[1];
    const float* W3   = (const float*)d_in[2];
    const float* b3   = (const float*)d_in[3];
    const float* W5   = (const float*)d_in[4];
    const float* b5   = (const float*)d_in[5];
    const float* W7   = (const float*)d_in[6];
    const float* b7   = (const float*)d_in[7];
    const float* w1   = (const float*)d_in[8];
    const float* bm1  = (const float*)d_in[9];
    const float* w2   = (const float*)d_in[10];
    const float* bm2  = (const float*)d_in[11];
    const float* g1   = (const float*)d_in[12];
    const float* be1  = (const float*)d_in[13];
    const float* g2   = (const float*)d_in[14];
    const float* be2  = (const float*)d_in[15];
    float* out = (float*)d_out;

    __half *xa, *c1, *c2, *hh, *t, *wc, *w1p, *w2p;
    cudaGetSymbolAddress((void**)&xa, g_xa);
    cudaGetSymbolAddress((void**)&c1, g_c1);
    cudaGetSymbolAddress((void**)&c2, g_c2);
    cudaGetSymbolAddress((void**)&hh, g_hh);
    cudaGetSymbolAddress((void**)&t,  g_t);
    cudaGetSymbolAddress((void**)&wc,  g_wc);
    cudaGetSymbolAddress((void**)&w1p, g_w1);
    cudaGetSymbolAddress((void**)&w2p, g_w2);

    const int SMEMSZ = 3 * 2 * 128 * 72 * 2;   // 110592 B -> 2 CTAs/SM
    cudaFuncSetAttribute(gemm_mma<0,3,DQ,DQ>,  cudaFuncAttributeMaxDynamicSharedMemorySize, SMEMSZ);
    cudaFuncSetAttribute(gemm_mma<0,5,DQ,DQ>,  cudaFuncAttributeMaxDynamicSharedMemorySize, SMEMSZ);
    cudaFuncSetAttribute(gemm_mma<0,7,DQ,DQ>,  cudaFuncAttributeMaxDynamicSharedMemorySize, SMEMSZ);
    cudaFuncSetAttribute(gemm_mma<1,1,DQ,D4Q>, cudaFuncAttributeMaxDynamicSharedMemorySize, SMEMSZ);
    cudaFuncSetAttribute(gemm_mma<2,1,D4Q,DQ>, cudaFuncAttributeMaxDynamicSharedMemorySize, SMEMSZ);

    // prep
    prep_conv_all<<<(DQ*DQ + 255)/256, 256>>>(W3, W5, W7, wc);
    transpose_f2h<<<dim3(D4Q/32, DQ/32), dim3(32, 8)>>>(w1, w1p, DQ, D4Q);
    transpose_f2h<<<dim3(DQ/32, D4Q/32), dim3(32, 8)>>>(w2, w2p, D4Q, DQ);
    convert_x<<<MQ*DQ/2048, 256>>>(x, xa);

    // conv chain
    dim3 cgrid(LQ/128, DQ/128, BQ);
    gemm_mma<0,3,DQ,DQ><<<cgrid, 256, SMEMSZ>>>(xa, chain, wc,           b3, c1);
    gemm_mma<0,5,DQ,DQ><<<cgrid, 256, SMEMSZ>>>(c1, chain, wc + 3*DQ*DQ, b5, c2);
    gemm_mma<0,7,DQ,DQ><<<cgrid, 256, SMEMSZ>>>(c2, chain, wc + 8*DQ*DQ, b7, c1);

    // h = LN1(x + conv) -> fp16
    ln1_kernel<<<MQ/8, 256>>>(x, c1, g1, be1, hh);

    // MLP (mlp2 output fp16 into c2)
    gemm_mma<1,1,DQ,D4Q><<<dim3(MQ/128, D4Q/128, 1), 256, SMEMSZ>>>(hh, nullptr, w1p, bm1, t);
    gemm_mma<2,1,D4Q,DQ><<<dim3(MQ/128, DQ/128, 1),  256, SMEMSZ>>>(t,  nullptr, w2p, bm2, c2);

    // out = LN2(h + mlp)
    ln2_kernel<<<MQ/8, 256>>>(hh, c2, g2, be2, out);
}